// round 9
// baseline (speedup 1.0000x reference)
#include <cuda_runtime.h>
#include <math.h>

#define NB 8
#define FH 120
#define FW 160
#define NPIX (FH*FW)
#define NSEM 16
#define NC 20
#define MS 480
#define MS2 (MS*MS)
#define TCH 18            // tile channels: 0=fp_map, 1=fp_exp, 2..17=sem
#define HPC 20            // padded interleaved hp channels (5 x float4)
#define VRD 100
#define CELLS (VRD*VRD)
#define RB 160            // compact rot tile side (max bbox ~149)
#define RB2 (RB*RB)

// scratch (static device memory: allowed)
__device__ float4 g_hp4[(size_t)NB*CELLS*5];          // 6.4 MB, L2-resident
__device__ float  g_rotc[(size_t)NB*TCH*RB2];         // compact rotated planes
__device__ int    g_bbox[NB][8];                      // [0..3] rot bbox ; [4..7] translated bbox

__device__ __forceinline__ void red_v4(float* p, float a, float b, float c, float d) {
    asm volatile("red.global.add.v4.f32 [%0], {%1, %2, %3, %4};"
                 :: "l"(p), "f"(a), "f"(b), "f"(c), "f"(d) : "memory");
}

// bbox + translated bbox (8 threads of block 0) + zero g_hp4 (all threads)
__global__ void k_bbox_zero(const float* __restrict__ poses) {
    size_t i = blockIdx.x*(size_t)blockDim.x + threadIdx.x;
    if (i < (size_t)NB*CELLS*5) g_hp4[i] = make_float4(0.f, 0.f, 0.f, 0.f);
    if (blockIdx.x != 0 || threadIdx.x >= NB) return;
    int b = threadIdx.x;
    float th = (90.0f - poses[b*3+2]) * 0.017453292519943295f;
    float ct = cosf(th), st = sinf(th);
    const float gxlo = 189.0f/239.5f - 1.0f, gxhi = 290.0f/239.5f - 1.0f;
    const float gylo = 239.0f/239.5f - 1.0f, gyhi = 340.0f/239.5f - 1.0f;
    float gxs[2] = {gxlo, gxhi}, gys[2] = {gylo, gyhi};
    float xmn = 1e9f, xmx = -1e9f, ymn = 1e9f, ymx = -1e9f;
    #pragma unroll
    for (int a = 0; a < 2; a++)
        #pragma unroll
        for (int c = 0; c < 2; c++) {
            float gx = gxs[a], gy = gys[c];
            float x =  ct*gx + st*gy;
            float y = -st*gx + ct*gy;
            xmn = fminf(xmn, x); xmx = fmaxf(xmx, x);
            ymn = fminf(ymn, y); ymx = fmaxf(ymx, y);
        }
    int jmn = (int)floorf((xmn + 1.0f)*240.0f - 0.5f) - 2;
    int jmx = (int)ceilf ((xmx + 1.0f)*240.0f - 0.5f) + 2;
    int imn = (int)floorf((ymn + 1.0f)*240.0f - 0.5f) - 2;
    int imx = (int)ceilf ((ymx + 1.0f)*240.0f - 0.5f) + 2;
    int i0 = max(imn, 0), i1 = min(imx, MS-1);
    int j0 = max(jmn, 0), j1 = min(jmx, MS-1);
    g_bbox[b][0] = i0; g_bbox[b][1] = i1;
    g_bbox[b][2] = j0; g_bbox[b][3] = j1;

    float pxp = poses[b*3+0], pyp = poses[b*3+1];
    float stx = -((pxp*100.0f)/5.0f - 240.0f)/240.0f;
    float sty = -((pyp*100.0f)/5.0f - 240.0f)/240.0f;
    const float A = 239.5f/240.0f;
    float cy = 239.5f/480.0f + 239.5f*sty;
    int ti0 = (int)floorf(((float)(i0-1) - cy)/A) - 1;
    int ti1 = (int)ceilf (((float)(i1+1) - cy)/A) + 1;
    float cx = 239.5f/480.0f + 239.5f*stx;
    int tj0 = (int)floorf(((float)(j0-1) - cx)/A) - 1;
    int tj1 = (int)ceilf (((float)(j1+1) - cx)/A) + 1;
    g_bbox[b][4] = max(ti0, 0); g_bbox[b][5] = min(ti1, MS-1);
    g_bbox[b][6] = max(tj0, 0); g_bbox[b][7] = min(tj1, MS-1);
}

// one thread per pixel; vector reductions into interleaved hp
__global__ void k_splat(const float* __restrict__ obs, float f_cam) {
    int t = blockIdx.x*blockDim.x + threadIdx.x;
    if (t >= NB*NPIX) return;
    int b = t / NPIX, pix = t % NPIX;
    int i = pix / FW, j = pix % FW;
    const float* ob = obs + (size_t)b*NC*NPIX;

    float d = ob[3*NPIX + pix] * 100.0f;               // depth cm (inputs never 0)
    float X = ((float)j - 79.5f) * d / f_cam + 250.0f;
    float Z = ((float)(FH-1-i) - 59.5f) * d / f_cam + 88.0f;
    float pos0 = X / 5.0f;
    float pos1 = d / 5.0f;
    float pos2 = Z / 5.0f + 8.0f;

    float fl0 = floorf(pos0), fl1 = floorf(pos1), fl2 = floorf(pos2);
    float p0f[2] = {fl0, fl0+1.0f}, p1f[2] = {fl1, fl1+1.0f};
    float w0[2], w1[2];
    #pragma unroll
    for (int k = 0; k < 2; k++) {
        w0[k] = (1.0f - fabsf(pos0 - p0f[k])) * ((p0f[k] > 0.0f && p0f[k] < 100.0f) ? 1.0f : 0.0f);
        w1[k] = (1.0f - fabsf(pos1 - p1f[k])) * ((p1f[k] > 0.0f && p1f[k] < 100.0f) ? 1.0f : 0.0f);
    }
    float wze = 0.0f, wza = 0.0f;
    #pragma unroll
    for (int k = 0; k < 2; k++) {
        float p = fl2 + (float)k;
        if (p > 0.0f && p < 80.0f) {
            float wz = 1.0f - fabsf(pos2 - p);
            wze += wz;
            int zi = (int)p;
            if (zi >= 13 && zi < 25) wza += wz;
        }
    }
    if (wze <= 0.0f && wza <= 0.0f) return;
    if (w0[0] == 0.0f && w0[1] == 0.0f) return;
    if (w1[0] == 0.0f && w1[1] == 0.0f) return;

    bool agent = (wza > 0.0f);
    float sem[NSEM];
    #pragma unroll
    for (int s = 0; s < NSEM; s++) sem[s] = 0.0f;
    if (agent) {
        #pragma unroll
        for (int s = 0; s < NSEM; s++) sem[s] = ob[(4+s)*NPIX + pix];
    }

    float* hpb = (float*)(g_hp4 + (size_t)b*CELLS*5);
    #pragma unroll
    for (int a = 0; a < 2; a++) {
        if (w0[a] == 0.0f) continue;
        int ix = (int)p0f[a];
        #pragma unroll
        for (int c2 = 0; c2 < 2; c2++) {
            if (w1[c2] == 0.0f) continue;
            int iy = (int)p1f[c2];
            float wxy = w0[a]*w1[c2];
            float wag = wxy*wza;
            float* cp = hpb + (size_t)(iy*VRD + ix)*HPC;
            red_v4(cp, wxy*wze, wag, wag*sem[0], wag*sem[1]);
            if (agent) {
                red_v4(cp+4,  wag*sem[2],  wag*sem[3],  wag*sem[4],  wag*sem[5]);
                red_v4(cp+8,  wag*sem[6],  wag*sem[7],  wag*sem[8],  wag*sem[9]);
                red_v4(cp+12, wag*sem[10], wag*sem[11], wag*sem[12], wag*sem[13]);
                red_v4(cp+16, wag*sem[14], wag*sem[15], 0.0f, 0.0f);
            }
        }
    }
}

// rotation grid_sample; branchless taps -> all 12 LDG.128 issued up front.
// blockIdx.z picks channel group (0: tile 0..8, 1: tile 9..17)
__global__ void k_rotate(const float* __restrict__ poses) {
    int b  = blockIdx.y;
    int grp = blockIdx.z;
    int t  = blockIdx.x*blockDim.x + threadIdx.x;
    int i0 = g_bbox[b][0], i1 = g_bbox[b][1], j0 = g_bbox[b][2], j1 = g_bbox[b][3];
    int w  = j1 - j0 + 1, h = i1 - i0 + 1;
    int li = t / w, lj = t % w;
    if (li >= h) return;
    int r = i0 + li, col = j0 + lj;

    float th = (90.0f - poses[b*3+2]) * 0.017453292519943295f;
    float ct = cosf(th), st = sinf(th);
    float x = (2.0f*col + 1.0f)/480.0f - 1.0f;
    float y = (2.0f*r   + 1.0f)/480.0f - 1.0f;
    float gx = ct*x - st*y;
    float gy = st*x + ct*y;
    float xs = (gx + 1.0f)*0.5f*479.0f;
    float ys = (gy + 1.0f)*0.5f*479.0f;
    float x0f = floorf(xs), y0f = floorf(ys);

    // branchless tap weights + clamped local indices
    float wyv[2], wxv[2];
    int   lyi[2], lxi[2];
    #pragma unroll
    for (int k = 0; k < 2; k++) {
        float pyf = y0f + (float)k;
        int   yi  = (int)pyf;
        bool  ok  = (pyf >= 0.0f && pyf < 480.0f) && (yi >= 240 && yi < 340);
        wyv[k] = ok ? (1.0f - fabsf(ys - pyf)) : 0.0f;
        lyi[k] = min(max(yi - 240, 0), VRD-1);
        float pxf = x0f + (float)k;
        int   xi  = (int)pxf;
        bool  okx = (pxf >= 0.0f && pxf < 480.0f) && (xi >= 190 && xi < 290);
        wxv[k] = okx ? (1.0f - fabsf(xs - pxf)) : 0.0f;
        lxi[k] = min(max(xi - 190, 0), VRD-1);
    }

    float acc[9];
    #pragma unroll
    for (int c = 0; c < 9; c++) acc[c] = 0.0f;

    const float4* hpb = g_hp4 + (size_t)b*CELLS*5;
    #pragma unroll
    for (int dy = 0; dy < 2; dy++) {
        #pragma unroll
        for (int dx = 0; dx < 2; dx++) {
            float wgt = wxv[dx]*wyv[dy];
            const float4* cp = hpb + (size_t)(lyi[dy]*VRD + lxi[dx])*5;
            if (grp == 0) {
                float4 t0 = cp[0], t1 = cp[1], t2 = cp[2];
                acc[0] += wgt * fminf(t0.y, 1.0f);
                acc[1] += wgt * fminf(t0.x, 1.0f);
                acc[2] += wgt * fminf(t0.z*0.2f, 1.0f);
                acc[3] += wgt * fminf(t0.w*0.2f, 1.0f);
                acc[4] += wgt * fminf(t1.x*0.2f, 1.0f);
                acc[5] += wgt * fminf(t1.y*0.2f, 1.0f);
                acc[6] += wgt * fminf(t1.z*0.2f, 1.0f);
                acc[7] += wgt * fminf(t1.w*0.2f, 1.0f);
                acc[8] += wgt * fminf(t2.x*0.2f, 1.0f);
            } else {
                float4 t2 = cp[2], t3 = cp[3], t4 = cp[4];
                acc[0] += wgt * fminf(t2.y*0.2f, 1.0f);
                acc[1] += wgt * fminf(t2.z*0.2f, 1.0f);
                acc[2] += wgt * fminf(t2.w*0.2f, 1.0f);
                acc[3] += wgt * fminf(t3.x*0.2f, 1.0f);
                acc[4] += wgt * fminf(t3.y*0.2f, 1.0f);
                acc[5] += wgt * fminf(t3.z*0.2f, 1.0f);
                acc[6] += wgt * fminf(t3.w*0.2f, 1.0f);
                acc[7] += wgt * fminf(t4.x*0.2f, 1.0f);
                acc[8] += wgt * fminf(t4.y*0.2f, 1.0f);
            }
        }
    }
    float* rp = g_rotc + (size_t)b*TCH*RB2 + (size_t)(grp*9)*RB2 + (size_t)li*RB + lj;
    #pragma unroll
    for (int c = 0; c < 9; c++) rp[(size_t)c*RB2] = acc[c];
}

// fused translation + max(maps_last) with translated-bbox fast path.
// 16 px per thread: grid(60, 19, 8), block(32,8), lanes 30..31 idle.
__global__ void __launch_bounds__(256) k_final(const float* __restrict__ maps_last,
                        const float* __restrict__ poses,
                        float* __restrict__ out) {
    int g = threadIdx.x;
    if (g >= 30) return;
    int r   = blockIdx.x*8 + threadIdx.y;
    int cp_ = blockIdx.y;
    int b   = blockIdx.z;
    int c   = (cp_ < 2) ? cp_ : cp_ + 1;
    int col0 = g << 4;
    size_t rowoff = (size_t)r*MS + col0;

    if (c == 3) {
        float pxp = poses[b*3+0], pyp = poses[b*3+1];
        size_t m3 = ((size_t)b*NC + 3)*MS2 + rowoff;
        size_t m2 = ((size_t)b*NC + 2)*MS2 + rowoff;
        float4 v[4];
        #pragma unroll
        for (int q = 0; q < 4; q++) v[q] = *(const float4*)(maps_last + m3 + 4*q);
        #pragma unroll
        for (int q = 0; q < 4; q++) *(float4*)(out + m2 + 4*q) = v[q];   // ch2 = pre-mask ch3
        int rr = (int)(pyp*100.0f/5.0f);
        int cc = (int)(pxp*100.0f/5.0f);
        if (abs(r - rr) <= 1) {
            #pragma unroll
            for (int q = 0; q < 4; q++) {
                float* vv = &v[q].x;
                #pragma unroll
                for (int p = 0; p < 4; p++)
                    if (abs(col0 + 4*q + p - cc) <= 1) vv[p] = 1.0f;
            }
        }
        #pragma unroll
        for (int q = 0; q < 4; q++) *(float4*)(out + m3 + 4*q) = v[q];
        return;
    }

    size_t mbase = ((size_t)b*NC + c)*MS2 + rowoff;
    float4 m[4];
    #pragma unroll
    for (int q = 0; q < 4; q++) m[q] = *(const float4*)(maps_last + mbase + 4*q);

    // fast path: outside translated window -> pure copy
    int ti0 = g_bbox[b][4], ti1 = g_bbox[b][5];
    int tj0 = g_bbox[b][6], tj1 = g_bbox[b][7];
    if (r < ti0 || r > ti1 || col0+15 < tj0 || col0 > tj1) {
        #pragma unroll
        for (int q = 0; q < 4; q++) *(float4*)(out + mbase + 4*q) = m[q];
        return;
    }

    float pxp = poses[b*3+0], pyp = poses[b*3+1];
    float stx = -((pxp*100.0f)/5.0f - 240.0f)/240.0f;
    float sty = -((pyp*100.0f)/5.0f - 240.0f)/240.0f;

    float ys  = ((2.0f*r + 1.0f)/480.0f + sty)*0.5f*479.0f;
    float y0f = floorf(ys);
    float wy0 = (y0f + 1.0f) - ys;
    float wy1 = ys - y0f;
    int   ry0 = (int)y0f, ry1 = ry0 + 1;
    int i0 = g_bbox[b][0], i1 = g_bbox[b][1], j0 = g_bbox[b][2], j1 = g_bbox[b][3];
    bool vy0 = (y0f      >= 0.0f && y0f      < 480.0f) && ry0 >= i0 && ry0 <= i1;
    bool vy1 = (y0f+1.0f >= 0.0f && y0f+1.0f < 480.0f) && ry1 >= i0 && ry1 <= i1;

    float tv[16];
    #pragma unroll
    for (int p = 0; p < 16; p++) tv[p] = 0.0f;
    if (vy0 || vy1) {
        int rc = (c < 2) ? c : (c - 2);
        const float* base = g_rotc + ((size_t)b*TCH + rc)*RB2;
        int ly0 = min(max(ry0 - i0, 0), RB-1);
        int ly1 = min(max(ry1 - i0, 0), RB-1);
        const float* row0 = base + (size_t)ly0*RB;
        const float* row1 = base + (size_t)ly1*RB;
        const float XSTEP = 479.0f/480.0f;
        float xs_base = ((2.0f*col0 + 1.0f)/480.0f + stx)*0.5f*479.0f;
        #pragma unroll
        for (int p = 0; p < 16; p++) {
            float xs  = fmaf((float)p, XSTEP, xs_base);
            float x0f = floorf(xs);
            float wx1 = xs - x0f;
            float wx0 = 1.0f - wx1;
            int   cx0 = (int)x0f;
            bool vx0 = (x0f      >= 0.0f && x0f      < 480.0f) && cx0   >= j0 && cx0   <= j1;
            bool vx1 = (x0f+1.0f >= 0.0f && x0f+1.0f < 480.0f) && cx0+1 >= j0 && cx0+1 <= j1;
            if (!(vx0 || vx1)) continue;
            int lx0 = min(max(cx0 - j0, 0), RB-2);
            float acc = 0.0f;
            if (vy0) {
                if (vx0) acc += wx0*wy0*row0[lx0];
                if (vx1) acc += wx1*wy0*row0[lx0+1];
            }
            if (vy1) {
                if (vx0) acc += wx0*wy1*row1[lx0];
                if (vx1) acc += wx1*wy1*row1[lx0+1];
            }
            tv[p] = acc;
        }
    }
    #pragma unroll
    for (int q = 0; q < 4; q++) {
        float4 o;
        o.x = fmaxf(m[q].x, tv[4*q+0]);
        o.y = fmaxf(m[q].y, tv[4*q+1]);
        o.z = fmaxf(m[q].z, tv[4*q+2]);
        o.w = fmaxf(m[q].w, tv[4*q+3]);
        *(float4*)(out + mbase + 4*q) = o;
    }
}

extern "C" void kernel_launch(void* const* d_in, const int* in_sizes, int n_in,
                              void* d_out, int out_size) {
    const float* obs       = (const float*)d_in[0];   // (8,20,120,160)
    const float* maps_last = (const float*)d_in[1];   // (8,20,480,480)
    const float* poses     = (const float*)d_in[2];   // (8,3)
    float* out = (float*)d_out;                       // (8,20,480,480)

    float f_cam = (float)((double)FW / 2.0 / tan(79.0/2.0 * 3.14159265358979323846/180.0));

    k_bbox_zero<<<((NB*CELLS*5) + 255)/256, 256>>>(poses);
    k_splat    <<<(NB*NPIX + 255)/256, 256>>>(obs, f_cam);
    k_rotate   <<<dim3((RB*RB + 255)/256, NB, 2), 256>>>(poses);
    k_final    <<<dim3(MS/8, NC-1, NB), dim3(32, 8)>>>(maps_last, poses, out);
}

// round 10
// speedup vs baseline: 1.3058x; 1.3058x over previous
#include <cuda_runtime.h>
#include <math.h>

#define NB 8
#define FH 120
#define FW 160
#define NPIX (FH*FW)
#define NSEM 16
#define NC 20
#define MS 480
#define MS2 (MS*MS)
#define TCH 18            // tile channels: 0=fp_map, 1=fp_exp, 2..17=sem
#define HPC 20            // padded interleaved hp channels (5 x float4)
#define VRD 100
#define CELLS (VRD*VRD)
#define RB 160            // compact rot tile side (max bbox ~149)
#define RB2 (RB*RB)

// scratch (static device memory: allowed)
__device__ float4 g_hp4[(size_t)NB*CELLS*5];          // 6.4 MB, L2-resident
__device__ float  g_rotc[(size_t)NB*TCH*RB2];         // compact rotated planes
__device__ int    g_bbox[NB][8];                      // [0..3] rot bbox ; [4..7] translated bbox

__device__ __forceinline__ void red_v4(float* p, float a, float b, float c, float d) {
    asm volatile("red.global.add.v4.f32 [%0], {%1, %2, %3, %4};"
                 :: "l"(p), "f"(a), "f"(b), "f"(c), "f"(d) : "memory");
}

// bbox + translated bbox (8 threads of block 0) + zero g_hp4 (all threads)
__global__ void k_bbox_zero(const float* __restrict__ poses) {
    size_t i = blockIdx.x*(size_t)blockDim.x + threadIdx.x;
    if (i < (size_t)NB*CELLS*5) g_hp4[i] = make_float4(0.f, 0.f, 0.f, 0.f);
    if (blockIdx.x != 0 || threadIdx.x >= NB) return;
    int b = threadIdx.x;
    float th = (90.0f - poses[b*3+2]) * 0.017453292519943295f;
    float ct = cosf(th), st = sinf(th);
    const float gxlo = 189.0f/239.5f - 1.0f, gxhi = 290.0f/239.5f - 1.0f;
    const float gylo = 239.0f/239.5f - 1.0f, gyhi = 340.0f/239.5f - 1.0f;
    float gxs[2] = {gxlo, gxhi}, gys[2] = {gylo, gyhi};
    float xmn = 1e9f, xmx = -1e9f, ymn = 1e9f, ymx = -1e9f;
    #pragma unroll
    for (int a = 0; a < 2; a++)
        #pragma unroll
        for (int c = 0; c < 2; c++) {
            float gx = gxs[a], gy = gys[c];
            float x =  ct*gx + st*gy;
            float y = -st*gx + ct*gy;
            xmn = fminf(xmn, x); xmx = fmaxf(xmx, x);
            ymn = fminf(ymn, y); ymx = fmaxf(ymx, y);
        }
    int jmn = (int)floorf((xmn + 1.0f)*240.0f - 0.5f) - 2;
    int jmx = (int)ceilf ((xmx + 1.0f)*240.0f - 0.5f) + 2;
    int imn = (int)floorf((ymn + 1.0f)*240.0f - 0.5f) - 2;
    int imx = (int)ceilf ((ymx + 1.0f)*240.0f - 0.5f) + 2;
    int i0 = max(imn, 0), i1 = min(imx, MS-1);
    int j0 = max(jmn, 0), j1 = min(jmx, MS-1);
    g_bbox[b][0] = i0; g_bbox[b][1] = i1;
    g_bbox[b][2] = j0; g_bbox[b][3] = j1;

    float pxp = poses[b*3+0], pyp = poses[b*3+1];
    float stx = -((pxp*100.0f)/5.0f - 240.0f)/240.0f;
    float sty = -((pyp*100.0f)/5.0f - 240.0f)/240.0f;
    const float A = 239.5f/240.0f;
    float cy = 239.5f/480.0f + 239.5f*sty;
    int ti0 = (int)floorf(((float)(i0-1) - cy)/A) - 1;
    int ti1 = (int)ceilf (((float)(i1+1) - cy)/A) + 1;
    float cx = 239.5f/480.0f + 239.5f*stx;
    int tj0 = (int)floorf(((float)(j0-1) - cx)/A) - 1;
    int tj1 = (int)ceilf (((float)(j1+1) - cx)/A) + 1;
    g_bbox[b][4] = max(ti0, 0); g_bbox[b][5] = min(ti1, MS-1);
    g_bbox[b][6] = max(tj0, 0); g_bbox[b][7] = min(tj1, MS-1);
}

// one thread per pixel; vector reductions into interleaved hp
__global__ void k_splat(const float* __restrict__ obs, float f_cam) {
    int t = blockIdx.x*blockDim.x + threadIdx.x;
    if (t >= NB*NPIX) return;
    int b = t / NPIX, pix = t % NPIX;
    int i = pix / FW, j = pix % FW;
    const float* ob = obs + (size_t)b*NC*NPIX;

    float d = ob[3*NPIX + pix] * 100.0f;               // depth cm (inputs never 0)
    float X = ((float)j - 79.5f) * d / f_cam + 250.0f;
    float Z = ((float)(FH-1-i) - 59.5f) * d / f_cam + 88.0f;
    float pos0 = X / 5.0f;
    float pos1 = d / 5.0f;
    float pos2 = Z / 5.0f + 8.0f;

    float fl0 = floorf(pos0), fl1 = floorf(pos1), fl2 = floorf(pos2);
    float p0f[2] = {fl0, fl0+1.0f}, p1f[2] = {fl1, fl1+1.0f};
    float w0[2], w1[2];
    #pragma unroll
    for (int k = 0; k < 2; k++) {
        w0[k] = (1.0f - fabsf(pos0 - p0f[k])) * ((p0f[k] > 0.0f && p0f[k] < 100.0f) ? 1.0f : 0.0f);
        w1[k] = (1.0f - fabsf(pos1 - p1f[k])) * ((p1f[k] > 0.0f && p1f[k] < 100.0f) ? 1.0f : 0.0f);
    }
    float wze = 0.0f, wza = 0.0f;
    #pragma unroll
    for (int k = 0; k < 2; k++) {
        float p = fl2 + (float)k;
        if (p > 0.0f && p < 80.0f) {
            float wz = 1.0f - fabsf(pos2 - p);
            wze += wz;
            int zi = (int)p;
            if (zi >= 13 && zi < 25) wza += wz;
        }
    }
    if (wze <= 0.0f && wza <= 0.0f) return;
    if (w0[0] == 0.0f && w0[1] == 0.0f) return;
    if (w1[0] == 0.0f && w1[1] == 0.0f) return;

    bool agent = (wza > 0.0f);
    float sem[NSEM];
    #pragma unroll
    for (int s = 0; s < NSEM; s++) sem[s] = 0.0f;
    if (agent) {
        #pragma unroll
        for (int s = 0; s < NSEM; s++) sem[s] = ob[(4+s)*NPIX + pix];
    }

    float* hpb = (float*)(g_hp4 + (size_t)b*CELLS*5);
    #pragma unroll
    for (int a = 0; a < 2; a++) {
        if (w0[a] == 0.0f) continue;
        int ix = (int)p0f[a];
        #pragma unroll
        for (int c2 = 0; c2 < 2; c2++) {
            if (w1[c2] == 0.0f) continue;
            int iy = (int)p1f[c2];
            float wxy = w0[a]*w1[c2];
            float wag = wxy*wza;
            float* cp = hpb + (size_t)(iy*VRD + ix)*HPC;
            red_v4(cp, wxy*wze, wag, wag*sem[0], wag*sem[1]);
            if (agent) {
                red_v4(cp+4,  wag*sem[2],  wag*sem[3],  wag*sem[4],  wag*sem[5]);
                red_v4(cp+8,  wag*sem[6],  wag*sem[7],  wag*sem[8],  wag*sem[9]);
                red_v4(cp+12, wag*sem[10], wag*sem[11], wag*sem[12], wag*sem[13]);
                red_v4(cp+16, wag*sem[14], wag*sem[15], 0.0f, 0.0f);
            }
        }
    }
}

// rotation grid_sample; branchless taps (neutral vs branched, simpler)
__global__ void k_rotate(const float* __restrict__ poses) {
    int b  = blockIdx.y;
    int grp = blockIdx.z;
    int t  = blockIdx.x*blockDim.x + threadIdx.x;
    int i0 = g_bbox[b][0], i1 = g_bbox[b][1], j0 = g_bbox[b][2], j1 = g_bbox[b][3];
    int w  = j1 - j0 + 1, h = i1 - i0 + 1;
    int li = t / w, lj = t % w;
    if (li >= h) return;
    int r = i0 + li, col = j0 + lj;

    float th = (90.0f - poses[b*3+2]) * 0.017453292519943295f;
    float ct = cosf(th), st = sinf(th);
    float x = (2.0f*col + 1.0f)/480.0f - 1.0f;
    float y = (2.0f*r   + 1.0f)/480.0f - 1.0f;
    float gx = ct*x - st*y;
    float gy = st*x + ct*y;
    float xs = (gx + 1.0f)*0.5f*479.0f;
    float ys = (gy + 1.0f)*0.5f*479.0f;
    float x0f = floorf(xs), y0f = floorf(ys);

    float wyv[2], wxv[2];
    int   lyi[2], lxi[2];
    #pragma unroll
    for (int k = 0; k < 2; k++) {
        float pyf = y0f + (float)k;
        int   yi  = (int)pyf;
        bool  ok  = (pyf >= 0.0f && pyf < 480.0f) && (yi >= 240 && yi < 340);
        wyv[k] = ok ? (1.0f - fabsf(ys - pyf)) : 0.0f;
        lyi[k] = min(max(yi - 240, 0), VRD-1);
        float pxf = x0f + (float)k;
        int   xi  = (int)pxf;
        bool  okx = (pxf >= 0.0f && pxf < 480.0f) && (xi >= 190 && xi < 290);
        wxv[k] = okx ? (1.0f - fabsf(xs - pxf)) : 0.0f;
        lxi[k] = min(max(xi - 190, 0), VRD-1);
    }

    float acc[9];
    #pragma unroll
    for (int c = 0; c < 9; c++) acc[c] = 0.0f;

    const float4* hpb = g_hp4 + (size_t)b*CELLS*5;
    #pragma unroll
    for (int dy = 0; dy < 2; dy++) {
        #pragma unroll
        for (int dx = 0; dx < 2; dx++) {
            float wgt = wxv[dx]*wyv[dy];
            const float4* cp = hpb + (size_t)(lyi[dy]*VRD + lxi[dx])*5;
            if (grp == 0) {
                float4 t0 = cp[0], t1 = cp[1], t2 = cp[2];
                acc[0] += wgt * fminf(t0.y, 1.0f);
                acc[1] += wgt * fminf(t0.x, 1.0f);
                acc[2] += wgt * fminf(t0.z*0.2f, 1.0f);
                acc[3] += wgt * fminf(t0.w*0.2f, 1.0f);
                acc[4] += wgt * fminf(t1.x*0.2f, 1.0f);
                acc[5] += wgt * fminf(t1.y*0.2f, 1.0f);
                acc[6] += wgt * fminf(t1.z*0.2f, 1.0f);
                acc[7] += wgt * fminf(t1.w*0.2f, 1.0f);
                acc[8] += wgt * fminf(t2.x*0.2f, 1.0f);
            } else {
                float4 t2 = cp[2], t3 = cp[3], t4 = cp[4];
                acc[0] += wgt * fminf(t2.y*0.2f, 1.0f);
                acc[1] += wgt * fminf(t2.z*0.2f, 1.0f);
                acc[2] += wgt * fminf(t2.w*0.2f, 1.0f);
                acc[3] += wgt * fminf(t3.x*0.2f, 1.0f);
                acc[4] += wgt * fminf(t3.y*0.2f, 1.0f);
                acc[5] += wgt * fminf(t3.z*0.2f, 1.0f);
                acc[6] += wgt * fminf(t3.w*0.2f, 1.0f);
                acc[7] += wgt * fminf(t4.x*0.2f, 1.0f);
                acc[8] += wgt * fminf(t4.y*0.2f, 1.0f);
            }
        }
    }
    float* rp = g_rotc + (size_t)b*TCH*RB2 + (size_t)(grp*9)*RB2 + (size_t)li*RB + lj;
    #pragma unroll
    for (int c = 0; c < 9; c++) rp[(size_t)c*RB2] = acc[c];
}

// fused translation + max(maps_last), translated-bbox fast path.
// grid(120, 19, 8), block(64,4). Thread t (0..59) handles float4 groups t and
// t+60 of its row: both LDG/STG are stride-16B across the warp (fully coalesced).
__global__ void __launch_bounds__(256) k_final(const float* __restrict__ maps_last,
                        const float* __restrict__ poses,
                        float* __restrict__ out) {
    int t = threadIdx.x;
    if (t >= 60) return;
    int r   = blockIdx.x*4 + threadIdx.y;
    int cp_ = blockIdx.y;
    int b   = blockIdx.z;
    int c   = (cp_ < 2) ? cp_ : cp_ + 1;
    int colA = t << 2;            // px 4t..4t+3
    int colB = colA + 240;        // px 4t+240..4t+243

    float pxp = poses[b*3+0], pyp = poses[b*3+1];
    size_t rbase = (size_t)r*MS;

    if (c == 3) {
        size_t m3 = ((size_t)b*NC + 3)*MS2 + rbase;
        size_t m2 = ((size_t)b*NC + 2)*MS2 + rbase;
        float4 vA = *(const float4*)(maps_last + m3 + colA);
        float4 vB = *(const float4*)(maps_last + m3 + colB);
        *(float4*)(out + m2 + colA) = vA;   // ch2 = pre-mask ch3
        *(float4*)(out + m2 + colB) = vB;
        int rr = (int)(pyp*100.0f/5.0f);
        int cc = (int)(pxp*100.0f/5.0f);
        if (abs(r - rr) <= 1) {
            float* a = &vA.x; float* bb = &vB.x;
            #pragma unroll
            for (int p = 0; p < 4; p++) {
                if (abs(colA+p - cc) <= 1) a[p] = 1.0f;
                if (abs(colB+p - cc) <= 1) bb[p] = 1.0f;
            }
        }
        *(float4*)(out + m3 + colA) = vA;
        *(float4*)(out + m3 + colB) = vB;
        return;
    }

    size_t mbase = ((size_t)b*NC + c)*MS2 + rbase;
    float4 mA = *(const float4*)(maps_last + mbase + colA);
    float4 mB = *(const float4*)(maps_last + mbase + colB);

    int ti0 = g_bbox[b][4], ti1 = g_bbox[b][5];
    int tj0 = g_bbox[b][6], tj1 = g_bbox[b][7];
    bool rowAct = (r >= ti0 && r <= ti1);
    bool actA = rowAct && !(colA+3 < tj0 || colA > tj1);
    bool actB = rowAct && !(colB+3 < tj0 || colB > tj1);

    if (!actA && !actB) {
        *(float4*)(out + mbase + colA) = mA;
        *(float4*)(out + mbase + colB) = mB;
        return;
    }

    float stx = -((pxp*100.0f)/5.0f - 240.0f)/240.0f;
    float sty = -((pyp*100.0f)/5.0f - 240.0f)/240.0f;

    float ys  = ((2.0f*r + 1.0f)/480.0f + sty)*0.5f*479.0f;
    float y0f = floorf(ys);
    float wy0 = (y0f + 1.0f) - ys;
    float wy1 = ys - y0f;
    int   ry0 = (int)y0f, ry1 = ry0 + 1;
    int i0 = g_bbox[b][0], i1 = g_bbox[b][1], j0 = g_bbox[b][2], j1 = g_bbox[b][3];
    bool vy0 = (y0f      >= 0.0f && y0f      < 480.0f) && ry0 >= i0 && ry0 <= i1;
    bool vy1 = (y0f+1.0f >= 0.0f && y0f+1.0f < 480.0f) && ry1 >= i0 && ry1 <= i1;

    int rc = (c < 2) ? c : (c - 2);
    const float* base = g_rotc + ((size_t)b*TCH + rc)*RB2;
    int ly0 = min(max(ry0 - i0, 0), RB-1);
    int ly1 = min(max(ry1 - i0, 0), RB-1);
    const float* row0 = base + (size_t)ly0*RB;
    const float* row1 = base + (size_t)ly1*RB;
    const float XSTEP = 479.0f/480.0f;
    bool anyY = vy0 || vy1;

    float4 oA = mA, oB = mB;
    #pragma unroll
    for (int hh = 0; hh < 2; hh++) {
        bool act = hh ? actB : actA;
        if (!act || !anyY) continue;
        int c0 = hh ? colB : colA;
        float4* o = hh ? &oB : &oA;
        float xs_base = ((2.0f*c0 + 1.0f)/480.0f + stx)*0.5f*479.0f;
        float* of = &o->x;
        #pragma unroll
        for (int p = 0; p < 4; p++) {
            float xs  = fmaf((float)p, XSTEP, xs_base);
            float x0f = floorf(xs);
            float wx1 = xs - x0f;
            float wx0 = 1.0f - wx1;
            int   cx0 = (int)x0f;
            bool vx0 = (x0f      >= 0.0f && x0f      < 480.0f) && cx0   >= j0 && cx0   <= j1;
            bool vx1 = (x0f+1.0f >= 0.0f && x0f+1.0f < 480.0f) && cx0+1 >= j0 && cx0+1 <= j1;
            if (!(vx0 || vx1)) continue;
            int lx0 = min(max(cx0 - j0, 0), RB-2);
            float acc = 0.0f;
            if (vy0) {
                if (vx0) acc += wx0*wy0*row0[lx0];
                if (vx1) acc += wx1*wy0*row0[lx0+1];
            }
            if (vy1) {
                if (vx0) acc += wx0*wy1*row1[lx0];
                if (vx1) acc += wx1*wy1*row1[lx0+1];
            }
            of[p] = fmaxf(of[p], acc);
        }
    }
    *(float4*)(out + mbase + colA) = oA;
    *(float4*)(out + mbase + colB) = oB;
}

extern "C" void kernel_launch(void* const* d_in, const int* in_sizes, int n_in,
                              void* d_out, int out_size) {
    const float* obs       = (const float*)d_in[0];   // (8,20,120,160)
    const float* maps_last = (const float*)d_in[1];   // (8,20,480,480)
    const float* poses     = (const float*)d_in[2];   // (8,3)
    float* out = (float*)d_out;                       // (8,20,480,480)

    float f_cam = (float)((double)FW / 2.0 / tan(79.0/2.0 * 3.14159265358979323846/180.0));

    k_bbox_zero<<<((NB*CELLS*5) + 255)/256, 256>>>(poses);
    k_splat    <<<(NB*NPIX + 255)/256, 256>>>(obs, f_cam);
    k_rotate   <<<dim3((RB*RB + 255)/256, NB, 2), 256>>>(poses);
    k_final    <<<dim3(MS/4, NC-1, NB), dim3(64, 4)>>>(maps_last, poses, out);
}

// round 11
// speedup vs baseline: 1.3565x; 1.0388x over previous
#include <cuda_runtime.h>
#include <math.h>

#define NB 8
#define FH 120
#define FW 160
#define NPIX (FH*FW)
#define NSEM 16
#define NC 20
#define MS 480
#define MS2 (MS*MS)
#define TCH 18            // tile channels: 0=fp_map, 1=fp_exp, 2..17=sem
#define HPC 20            // padded interleaved hp channels (5 x float4)
#define VRD 100
#define CELLS (VRD*VRD)
#define RB 160            // compact rot tile side (max bbox ~149)
#define RB2 (RB*RB)

// scratch (static device memory: allowed)
__device__ float4 g_hp4[(size_t)NB*CELLS*5];          // 6.4 MB, L2-resident
__device__ float  g_rotc[(size_t)NB*TCH*RB2];         // compact rotated planes
__device__ int    g_bbox[NB][8];                      // [0..3] rot bbox ; [4..7] translated bbox

__device__ __forceinline__ void red_v4(float* p, float a, float b, float c, float d) {
    asm volatile("red.global.add.v4.f32 [%0], {%1, %2, %3, %4};"
                 :: "l"(p), "f"(a), "f"(b), "f"(c), "f"(d) : "memory");
}

// bbox + translated bbox (8 threads of block 0) + zero g_hp4 (all threads)
__global__ void k_bbox_zero(const float* __restrict__ poses) {
    size_t i = blockIdx.x*(size_t)blockDim.x + threadIdx.x;
    if (i < (size_t)NB*CELLS*5) g_hp4[i] = make_float4(0.f, 0.f, 0.f, 0.f);
    if (blockIdx.x != 0 || threadIdx.x >= NB) return;
    int b = threadIdx.x;
    float th = (90.0f - poses[b*3+2]) * 0.017453292519943295f;
    float ct = cosf(th), st = sinf(th);
    const float gxlo = 189.0f/239.5f - 1.0f, gxhi = 290.0f/239.5f - 1.0f;
    const float gylo = 239.0f/239.5f - 1.0f, gyhi = 340.0f/239.5f - 1.0f;
    float gxs[2] = {gxlo, gxhi}, gys[2] = {gylo, gyhi};
    float xmn = 1e9f, xmx = -1e9f, ymn = 1e9f, ymx = -1e9f;
    #pragma unroll
    for (int a = 0; a < 2; a++)
        #pragma unroll
        for (int c = 0; c < 2; c++) {
            float gx = gxs[a], gy = gys[c];
            float x =  ct*gx + st*gy;
            float y = -st*gx + ct*gy;
            xmn = fminf(xmn, x); xmx = fmaxf(xmx, x);
            ymn = fminf(ymn, y); ymx = fmaxf(ymx, y);
        }
    int jmn = (int)floorf((xmn + 1.0f)*240.0f - 0.5f) - 2;
    int jmx = (int)ceilf ((xmx + 1.0f)*240.0f - 0.5f) + 2;
    int imn = (int)floorf((ymn + 1.0f)*240.0f - 0.5f) - 2;
    int imx = (int)ceilf ((ymx + 1.0f)*240.0f - 0.5f) + 2;
    int i0 = max(imn, 0), i1 = min(imx, MS-1);
    int j0 = max(jmn, 0), j1 = min(jmx, MS-1);
    g_bbox[b][0] = i0; g_bbox[b][1] = i1;
    g_bbox[b][2] = j0; g_bbox[b][3] = j1;

    float pxp = poses[b*3+0], pyp = poses[b*3+1];
    float stx = -((pxp*100.0f)/5.0f - 240.0f)/240.0f;
    float sty = -((pyp*100.0f)/5.0f - 240.0f)/240.0f;
    const float A = 239.5f/240.0f;
    float cy = 239.5f/480.0f + 239.5f*sty;
    int ti0 = (int)floorf(((float)(i0-1) - cy)/A) - 1;
    int ti1 = (int)ceilf (((float)(i1+1) - cy)/A) + 1;
    float cx = 239.5f/480.0f + 239.5f*stx;
    int tj0 = (int)floorf(((float)(j0-1) - cx)/A) - 1;
    int tj1 = (int)ceilf (((float)(j1+1) - cx)/A) + 1;
    g_bbox[b][4] = max(ti0, 0); g_bbox[b][5] = min(ti1, MS-1);
    g_bbox[b][6] = max(tj0, 0); g_bbox[b][7] = min(tj1, MS-1);
}

// one thread per pixel; vector reductions into interleaved hp
__global__ void k_splat(const float* __restrict__ obs, float f_cam) {
    int t = blockIdx.x*blockDim.x + threadIdx.x;
    if (t >= NB*NPIX) return;
    int b = t / NPIX, pix = t % NPIX;
    int i = pix / FW, j = pix % FW;
    const float* ob = obs + (size_t)b*NC*NPIX;

    float d = ob[3*NPIX + pix] * 100.0f;               // depth cm (inputs never 0)
    float X = ((float)j - 79.5f) * d / f_cam + 250.0f;
    float Z = ((float)(FH-1-i) - 59.5f) * d / f_cam + 88.0f;
    float pos0 = X / 5.0f;
    float pos1 = d / 5.0f;
    float pos2 = Z / 5.0f + 8.0f;

    float fl0 = floorf(pos0), fl1 = floorf(pos1), fl2 = floorf(pos2);
    float p0f[2] = {fl0, fl0+1.0f}, p1f[2] = {fl1, fl1+1.0f};
    float w0[2], w1[2];
    #pragma unroll
    for (int k = 0; k < 2; k++) {
        w0[k] = (1.0f - fabsf(pos0 - p0f[k])) * ((p0f[k] > 0.0f && p0f[k] < 100.0f) ? 1.0f : 0.0f);
        w1[k] = (1.0f - fabsf(pos1 - p1f[k])) * ((p1f[k] > 0.0f && p1f[k] < 100.0f) ? 1.0f : 0.0f);
    }
    float wze = 0.0f, wza = 0.0f;
    #pragma unroll
    for (int k = 0; k < 2; k++) {
        float p = fl2 + (float)k;
        if (p > 0.0f && p < 80.0f) {
            float wz = 1.0f - fabsf(pos2 - p);
            wze += wz;
            int zi = (int)p;
            if (zi >= 13 && zi < 25) wza += wz;
        }
    }
    if (wze <= 0.0f && wza <= 0.0f) return;
    if (w0[0] == 0.0f && w0[1] == 0.0f) return;
    if (w1[0] == 0.0f && w1[1] == 0.0f) return;

    bool agent = (wza > 0.0f);
    float sem[NSEM];
    #pragma unroll
    for (int s = 0; s < NSEM; s++) sem[s] = 0.0f;
    if (agent) {
        #pragma unroll
        for (int s = 0; s < NSEM; s++) sem[s] = ob[(4+s)*NPIX + pix];
    }

    float* hpb = (float*)(g_hp4 + (size_t)b*CELLS*5);
    #pragma unroll
    for (int a = 0; a < 2; a++) {
        if (w0[a] == 0.0f) continue;
        int ix = (int)p0f[a];
        #pragma unroll
        for (int c2 = 0; c2 < 2; c2++) {
            if (w1[c2] == 0.0f) continue;
            int iy = (int)p1f[c2];
            float wxy = w0[a]*w1[c2];
            float wag = wxy*wza;
            float* cp = hpb + (size_t)(iy*VRD + ix)*HPC;
            red_v4(cp, wxy*wze, wag, wag*sem[0], wag*sem[1]);
            if (agent) {
                red_v4(cp+4,  wag*sem[2],  wag*sem[3],  wag*sem[4],  wag*sem[5]);
                red_v4(cp+8,  wag*sem[6],  wag*sem[7],  wag*sem[8],  wag*sem[9]);
                red_v4(cp+12, wag*sem[10], wag*sem[11], wag*sem[12], wag*sem[13]);
                red_v4(cp+16, wag*sem[14], wag*sem[15], 0.0f, 0.0f);
            }
        }
    }
}

// rotation grid_sample; 3 channel groups of 6 (2 float4 hp loads per tap).
// grp0: tile ch 0..5 (hp floats {1,0,2,3,4,5} via t0,t1)
// grp1: tile ch 6..11 (hp 6..11 via t1,t2) ; grp2: tile ch 12..17 (hp 12..17 via t3,t4)
__global__ void k_rotate(const float* __restrict__ poses) {
    int b   = blockIdx.y;
    int grp = blockIdx.z;
    int t   = blockIdx.x*blockDim.x + threadIdx.x;
    int i0 = g_bbox[b][0], i1 = g_bbox[b][1], j0 = g_bbox[b][2], j1 = g_bbox[b][3];
    int w  = j1 - j0 + 1, h = i1 - i0 + 1;
    int li = t / w, lj = t % w;
    if (li >= h) return;
    int r = i0 + li, col = j0 + lj;

    float th = (90.0f - poses[b*3+2]) * 0.017453292519943295f;
    float ct = cosf(th), st = sinf(th);
    float x = (2.0f*col + 1.0f)/480.0f - 1.0f;
    float y = (2.0f*r   + 1.0f)/480.0f - 1.0f;
    float gx = ct*x - st*y;
    float gy = st*x + ct*y;
    float xs = (gx + 1.0f)*0.5f*479.0f;
    float ys = (gy + 1.0f)*0.5f*479.0f;
    float x0f = floorf(xs), y0f = floorf(ys);

    float wyv[2], wxv[2];
    int   lyi[2], lxi[2];
    #pragma unroll
    for (int k = 0; k < 2; k++) {
        float pyf = y0f + (float)k;
        int   yi  = (int)pyf;
        bool  ok  = (pyf >= 0.0f && pyf < 480.0f) && (yi >= 240 && yi < 340);
        wyv[k] = ok ? (1.0f - fabsf(ys - pyf)) : 0.0f;
        lyi[k] = min(max(yi - 240, 0), VRD-1);
        float pxf = x0f + (float)k;
        int   xi  = (int)pxf;
        bool  okx = (pxf >= 0.0f && pxf < 480.0f) && (xi >= 190 && xi < 290);
        wxv[k] = okx ? (1.0f - fabsf(xs - pxf)) : 0.0f;
        lxi[k] = min(max(xi - 190, 0), VRD-1);
    }

    float acc[6];
    #pragma unroll
    for (int c = 0; c < 6; c++) acc[c] = 0.0f;

    // float4 index pair per group
    int q0 = (grp == 0) ? 0 : (grp == 1) ? 1 : 3;
    int q1 = q0 + 1;

    const float4* hpb = g_hp4 + (size_t)b*CELLS*5;
    #pragma unroll
    for (int dy = 0; dy < 2; dy++) {
        #pragma unroll
        for (int dx = 0; dx < 2; dx++) {
            float wgt = wxv[dx]*wyv[dy];
            const float4* cp = hpb + (size_t)(lyi[dy]*VRD + lxi[dx])*5;
            float4 ta = cp[q0], tb = cp[q1];
            if (grp == 0) {
                acc[0] += wgt * fminf(ta.y, 1.0f);           // fp_map = clip(hp1)
                acc[1] += wgt * fminf(ta.x, 1.0f);           // fp_exp = clip(hp0)
                acc[2] += wgt * fminf(ta.z*0.2f, 1.0f);      // hp2
                acc[3] += wgt * fminf(ta.w*0.2f, 1.0f);      // hp3
                acc[4] += wgt * fminf(tb.x*0.2f, 1.0f);      // hp4
                acc[5] += wgt * fminf(tb.y*0.2f, 1.0f);      // hp5
            } else if (grp == 1) {
                acc[0] += wgt * fminf(ta.z*0.2f, 1.0f);      // hp6
                acc[1] += wgt * fminf(ta.w*0.2f, 1.0f);      // hp7
                acc[2] += wgt * fminf(tb.x*0.2f, 1.0f);      // hp8
                acc[3] += wgt * fminf(tb.y*0.2f, 1.0f);      // hp9
                acc[4] += wgt * fminf(tb.z*0.2f, 1.0f);      // hp10
                acc[5] += wgt * fminf(tb.w*0.2f, 1.0f);      // hp11
            } else {
                acc[0] += wgt * fminf(ta.x*0.2f, 1.0f);      // hp12
                acc[1] += wgt * fminf(ta.y*0.2f, 1.0f);      // hp13
                acc[2] += wgt * fminf(ta.z*0.2f, 1.0f);      // hp14
                acc[3] += wgt * fminf(ta.w*0.2f, 1.0f);      // hp15
                acc[4] += wgt * fminf(tb.x*0.2f, 1.0f);      // hp16
                acc[5] += wgt * fminf(tb.y*0.2f, 1.0f);      // hp17
            }
        }
    }
    float* rp = g_rotc + (size_t)b*TCH*RB2 + (size_t)(grp*6)*RB2 + (size_t)li*RB + lj;
    #pragma unroll
    for (int c = 0; c < 6; c++) rp[(size_t)c*RB2] = acc[c];
}

// fused translation + max(maps_last), translated-bbox fast path, coalesced halves,
// streaming loads/stores (touch-once traffic bypasses L2 retention).
__global__ void __launch_bounds__(256) k_final(const float* __restrict__ maps_last,
                        const float* __restrict__ poses,
                        float* __restrict__ out) {
    int t = threadIdx.x;
    if (t >= 60) return;
    int r   = blockIdx.x*4 + threadIdx.y;
    int cp_ = blockIdx.y;
    int b   = blockIdx.z;
    int c   = (cp_ < 2) ? cp_ : cp_ + 1;
    int colA = t << 2;            // px 4t..4t+3
    int colB = colA + 240;

    float pxp = poses[b*3+0], pyp = poses[b*3+1];
    size_t rbase = (size_t)r*MS;

    if (c == 3) {
        size_t m3 = ((size_t)b*NC + 3)*MS2 + rbase;
        size_t m2 = ((size_t)b*NC + 2)*MS2 + rbase;
        float4 vA = __ldcs((const float4*)(maps_last + m3 + colA));
        float4 vB = __ldcs((const float4*)(maps_last + m3 + colB));
        __stcs((float4*)(out + m2 + colA), vA);   // ch2 = pre-mask ch3
        __stcs((float4*)(out + m2 + colB), vB);
        int rr = (int)(pyp*100.0f/5.0f);
        int cc = (int)(pxp*100.0f/5.0f);
        if (abs(r - rr) <= 1) {
            float* a = &vA.x; float* bb = &vB.x;
            #pragma unroll
            for (int p = 0; p < 4; p++) {
                if (abs(colA+p - cc) <= 1) a[p] = 1.0f;
                if (abs(colB+p - cc) <= 1) bb[p] = 1.0f;
            }
        }
        __stcs((float4*)(out + m3 + colA), vA);
        __stcs((float4*)(out + m3 + colB), vB);
        return;
    }

    size_t mbase = ((size_t)b*NC + c)*MS2 + rbase;
    float4 mA = __ldcs((const float4*)(maps_last + mbase + colA));
    float4 mB = __ldcs((const float4*)(maps_last + mbase + colB));

    int ti0 = g_bbox[b][4], ti1 = g_bbox[b][5];
    int tj0 = g_bbox[b][6], tj1 = g_bbox[b][7];
    bool rowAct = (r >= ti0 && r <= ti1);
    bool actA = rowAct && !(colA+3 < tj0 || colA > tj1);
    bool actB = rowAct && !(colB+3 < tj0 || colB > tj1);

    if (!actA && !actB) {
        __stcs((float4*)(out + mbase + colA), mA);
        __stcs((float4*)(out + mbase + colB), mB);
        return;
    }

    float stx = -((pxp*100.0f)/5.0f - 240.0f)/240.0f;
    float sty = -((pyp*100.0f)/5.0f - 240.0f)/240.0f;

    float ys  = ((2.0f*r + 1.0f)/480.0f + sty)*0.5f*479.0f;
    float y0f = floorf(ys);
    float wy0 = (y0f + 1.0f) - ys;
    float wy1 = ys - y0f;
    int   ry0 = (int)y0f, ry1 = ry0 + 1;
    int i0 = g_bbox[b][0], i1 = g_bbox[b][1], j0 = g_bbox[b][2], j1 = g_bbox[b][3];
    bool vy0 = (y0f      >= 0.0f && y0f      < 480.0f) && ry0 >= i0 && ry0 <= i1;
    bool vy1 = (y0f+1.0f >= 0.0f && y0f+1.0f < 480.0f) && ry1 >= i0 && ry1 <= i1;

    int rc = (c < 2) ? c : (c - 2);
    const float* base = g_rotc + ((size_t)b*TCH + rc)*RB2;
    int ly0 = min(max(ry0 - i0, 0), RB-1);
    int ly1 = min(max(ry1 - i0, 0), RB-1);
    const float* row0 = base + (size_t)ly0*RB;
    const float* row1 = base + (size_t)ly1*RB;
    const float XSTEP = 479.0f/480.0f;
    bool anyY = vy0 || vy1;

    float4 oA = mA, oB = mB;
    #pragma unroll
    for (int hh = 0; hh < 2; hh++) {
        bool act = hh ? actB : actA;
        if (!act || !anyY) continue;
        int c0 = hh ? colB : colA;
        float4* o = hh ? &oB : &oA;
        float xs_base = ((2.0f*c0 + 1.0f)/480.0f + stx)*0.5f*479.0f;
        float* of = &o->x;
        #pragma unroll
        for (int p = 0; p < 4; p++) {
            float xs  = fmaf((float)p, XSTEP, xs_base);
            float x0f = floorf(xs);
            float wx1 = xs - x0f;
            float wx0 = 1.0f - wx1;
            int   cx0 = (int)x0f;
            bool vx0 = (x0f      >= 0.0f && x0f      < 480.0f) && cx0   >= j0 && cx0   <= j1;
            bool vx1 = (x0f+1.0f >= 0.0f && x0f+1.0f < 480.0f) && cx0+1 >= j0 && cx0+1 <= j1;
            if (!(vx0 || vx1)) continue;
            int lx0 = min(max(cx0 - j0, 0), RB-2);
            float acc = 0.0f;
            if (vy0) {
                if (vx0) acc += wx0*wy0*row0[lx0];
                if (vx1) acc += wx1*wy0*row0[lx0+1];
            }
            if (vy1) {
                if (vx0) acc += wx0*wy1*row1[lx0];
                if (vx1) acc += wx1*wy1*row1[lx0+1];
            }
            of[p] = fmaxf(of[p], acc);
        }
    }
    __stcs((float4*)(out + mbase + colA), oA);
    __stcs((float4*)(out + mbase + colB), oB);
}

extern "C" void kernel_launch(void* const* d_in, const int* in_sizes, int n_in,
                              void* d_out, int out_size) {
    const float* obs       = (const float*)d_in[0];   // (8,20,120,160)
    const float* maps_last = (const float*)d_in[1];   // (8,20,480,480)
    const float* poses     = (const float*)d_in[2];   // (8,3)
    float* out = (float*)d_out;                       // (8,20,480,480)

    float f_cam = (float)((double)FW / 2.0 / tan(79.0/2.0 * 3.14159265358979323846/180.0));

    k_bbox_zero<<<((NB*CELLS*5) + 255)/256, 256>>>(poses);
    k_splat    <<<(NB*NPIX + 255)/256, 256>>>(obs, f_cam);
    k_rotate   <<<dim3((RB*RB + 255)/256, NB, 3), 256>>>(poses);
    k_final    <<<dim3(MS/4, NC-1, NB), dim3(64, 4)>>>(maps_last, poses, out);
}